// round 1
// baseline (speedup 1.0000x reference)
#include <cuda_runtime.h>
#include <cstdint>

#define N_NODES 500000
#define N_EDGES 5000000
#define N_GRAPHS 5000
#define FEAT 7
#define STATE 16
#define ROUNDS 4

// Scratch (allocation-free rule: __device__ globals)
__device__ float g_state[N_NODES * STATE];
__device__ float g_msg[N_NODES * STATE];
__device__ float g_agg[N_NODES * STATE];

// ---------------- input layer: state = relu(x @ in_W + in_b) ----------------
__global__ void input_kernel(const float* __restrict__ x,
                             const float* __restrict__ W,
                             const float* __restrict__ b) {
    __shared__ float sW[FEAT * STATE];
    __shared__ float sb[STATE];
    int t = threadIdx.x;
    if (t < FEAT * STATE) sW[t] = W[t];
    if (t < STATE) sb[t] = b[t];
    __syncthreads();

    int i = blockIdx.x * blockDim.x + t;
    if (i >= N_NODES) return;

    float xi[FEAT];
#pragma unroll
    for (int k = 0; k < FEAT; k++) xi[k] = x[(size_t)i * FEAT + k];

    float o[STATE];
#pragma unroll
    for (int j = 0; j < STATE; j++) {
        float acc = sb[j];
#pragma unroll
        for (int k = 0; k < FEAT; k++) acc = fmaf(xi[k], sW[k * STATE + j], acc);
        o[j] = fmaxf(acc, 0.f);
    }
    float4* dst = reinterpret_cast<float4*>(g_state + (size_t)i * STATE);
#pragma unroll
    for (int v = 0; v < 4; v++)
        dst[v] = make_float4(o[4 * v], o[4 * v + 1], o[4 * v + 2], o[4 * v + 3]);
}

// ------ message = relu(state @ msg_W[r] + msg_b[r]);  also zero agg ------
__global__ void msg_kernel(const float* __restrict__ W,
                           const float* __restrict__ b) {
    __shared__ float sW[STATE * STATE];
    __shared__ float sb[STATE];
    int t = threadIdx.x;
    if (t < STATE * STATE) sW[t] = W[t];
    if (t < STATE) sb[t] = b[t];
    __syncthreads();

    int i = blockIdx.x * blockDim.x + t;
    if (i >= N_NODES) return;

    float s[STATE];
    const float4* sp = reinterpret_cast<const float4*>(g_state + (size_t)i * STATE);
#pragma unroll
    for (int v = 0; v < 4; v++) {
        float4 f = sp[v];
        s[4 * v] = f.x; s[4 * v + 1] = f.y; s[4 * v + 2] = f.z; s[4 * v + 3] = f.w;
    }

    float o[STATE];
#pragma unroll
    for (int j = 0; j < STATE; j++) {
        float acc = sb[j];
#pragma unroll
        for (int k = 0; k < STATE; k++) acc = fmaf(s[k], sW[k * STATE + j], acc);
        o[j] = fmaxf(acc, 0.f);
    }

    float4* mp = reinterpret_cast<float4*>(g_msg + (size_t)i * STATE);
    float4* ap = reinterpret_cast<float4*>(g_agg + (size_t)i * STATE);
    float4 z = make_float4(0.f, 0.f, 0.f, 0.f);
#pragma unroll
    for (int v = 0; v < 4; v++) {
        mp[v] = make_float4(o[4 * v], o[4 * v + 1], o[4 * v + 2], o[4 * v + 3]);
        ap[v] = z;
    }
}

// ------------- edge scatter: agg[dst] += msg[src] -------------
__device__ __forceinline__ void red_add_v4(float* addr, float4 v) {
    asm volatile("red.global.add.v4.f32 [%0], {%1, %2, %3, %4};"
                 :: "l"(addr), "f"(v.x), "f"(v.y), "f"(v.z), "f"(v.w)
                 : "memory");
}

__global__ void edge_kernel(const int* __restrict__ ei) {
    int e = blockIdx.x * blockDim.x + threadIdx.x;
    if (e >= N_EDGES) return;
    int s = ei[e];
    int d = ei[N_EDGES + e];
    const float4* m = reinterpret_cast<const float4*>(g_msg + (size_t)s * STATE);
    float* a = g_agg + (size_t)d * STATE;
    float4 m0 = m[0], m1 = m[1], m2 = m[2], m3 = m[3];
    red_add_v4(a + 0, m0);
    red_add_v4(a + 4, m1);
    red_add_v4(a + 8, m2);
    red_add_v4(a + 12, m3);
}

// ------------- state += relu(agg @ upd_W[r] + upd_b[r]) -------------
__global__ void upd_kernel(const float* __restrict__ W,
                           const float* __restrict__ b) {
    __shared__ float sW[STATE * STATE];
    __shared__ float sb[STATE];
    int t = threadIdx.x;
    if (t < STATE * STATE) sW[t] = W[t];
    if (t < STATE) sb[t] = b[t];
    __syncthreads();

    int i = blockIdx.x * blockDim.x + t;
    if (i >= N_NODES) return;

    float a[STATE];
    const float4* ap = reinterpret_cast<const float4*>(g_agg + (size_t)i * STATE);
#pragma unroll
    for (int v = 0; v < 4; v++) {
        float4 f = ap[v];
        a[4 * v] = f.x; a[4 * v + 1] = f.y; a[4 * v + 2] = f.z; a[4 * v + 3] = f.w;
    }

    float4* sp = reinterpret_cast<float4*>(g_state + (size_t)i * STATE);
    float4 st[4];
#pragma unroll
    for (int v = 0; v < 4; v++) st[v] = sp[v];
    float* stf = reinterpret_cast<float*>(st);

#pragma unroll
    for (int j = 0; j < STATE; j++) {
        float acc = sb[j];
#pragma unroll
        for (int k = 0; k < STATE; k++) acc = fmaf(a[k], sW[k * STATE + j], acc);
        stf[j] += fmaxf(acc, 0.f);
    }
#pragma unroll
    for (int v = 0; v < 4; v++) sp[v] = st[v];
}

// ------------- readout -------------
__global__ void out_init(const float* __restrict__ out_b, float* __restrict__ out) {
    int g = blockIdx.x * blockDim.x + threadIdx.x;
    if (g < N_GRAPHS) out[g] = out_b[0];
}

__global__ void readout_kernel(const int* __restrict__ batch,
                               const float* __restrict__ out_W,
                               float* __restrict__ out) {
    __shared__ float sw[STATE];
    int t = threadIdx.x;
    if (t < STATE) sw[t] = out_W[t];
    __syncthreads();

    int i = blockIdx.x * blockDim.x + t;
    if (i >= N_NODES) return;

    const float* s = g_state + (size_t)i * STATE;
    float acc = 0.f;
#pragma unroll
    for (int k = 0; k < STATE; k++) acc = fmaf(s[k], sw[k], acc);
    atomicAdd(&out[batch[i]], acc);
}

extern "C" void kernel_launch(void* const* d_in, const int* in_sizes, int n_in,
                              void* d_out, int out_size) {
    const float* x     = (const float*)d_in[0];
    const int*   ei    = (const int*)d_in[1];
    const int*   batch = (const int*)d_in[2];
    const float* in_W  = (const float*)d_in[3];
    const float* in_b  = (const float*)d_in[4];
    const float* msg_W = (const float*)d_in[5];
    const float* msg_b = (const float*)d_in[6];
    const float* upd_W = (const float*)d_in[7];
    const float* upd_b = (const float*)d_in[8];
    const float* out_W = (const float*)d_in[9];
    const float* out_b = (const float*)d_in[10];
    float* out = (float*)d_out;

    const int TB = 256;
    int node_blocks = (N_NODES + TB - 1) / TB;
    int edge_blocks = (N_EDGES + TB - 1) / TB;

    input_kernel<<<node_blocks, TB>>>(x, in_W, in_b);
    for (int r = 0; r < ROUNDS; r++) {
        msg_kernel<<<node_blocks, TB>>>(msg_W + r * STATE * STATE, msg_b + r * STATE);
        edge_kernel<<<edge_blocks, TB>>>(ei);
        upd_kernel<<<node_blocks, TB>>>(upd_W + r * STATE * STATE, upd_b + r * STATE);
    }
    out_init<<<(N_GRAPHS + TB - 1) / TB, TB>>>(out_b, out);
    readout_kernel<<<node_blocks, TB>>>(batch, out_W, out);
}

// round 2
// speedup vs baseline: 1.4144x; 1.4144x over previous
#include <cuda_runtime.h>
#include <cstdint>

#define N_NODES 500000
#define N_EDGES 5000000
#define N_GRAPHS 5000
#define FEAT 7
#define STATE 16
#define ROUNDS 4

#define SCAN_CHUNK 1024
#define SCAN_T 256
#define SCAN_NB ((N_NODES + SCAN_CHUNK - 1) / SCAN_CHUNK)   // 489

// ---- scratch (__device__ globals; no allocs allowed) ----
__device__ float g_state[N_NODES * STATE];
__device__ float g_msg_a[N_NODES * STATE];
__device__ float g_msg_b[N_NODES * STATE];
__device__ int   g_cnt[N_NODES];
__device__ int   g_excl[N_NODES];
__device__ int   g_bsum[SCAN_NB];
__device__ int   g_ptr[N_NODES + 1];
__device__ int   g_fill[N_NODES];
__device__ int   g_csr_src[N_EDGES];

// ================= CSR build =================
__global__ void zero_cnt_kernel() {
    int i = blockIdx.x * blockDim.x + threadIdx.x;
    if (i < N_NODES) g_cnt[i] = 0;
}

__global__ void hist_kernel(const int* __restrict__ ei) {
    int e = blockIdx.x * blockDim.x + threadIdx.x;
    if (e < N_EDGES) atomicAdd(&g_cnt[ei[N_EDGES + e]], 1);
}

// block-local exclusive scan over chunks of 1024 (4 elems/thread)
__global__ void scan1_kernel() {
    __shared__ int sh[SCAN_T];
    int b = blockIdx.x, t = threadIdx.x;
    int base = b * SCAN_CHUNK + t * 4;
    int v[4];
#pragma unroll
    for (int k = 0; k < 4; k++) {
        int idx = base + k;
        v[k] = (idx < N_NODES) ? g_cnt[idx] : 0;
    }
    int s = v[0] + v[1] + v[2] + v[3];
    sh[t] = s;
    __syncthreads();
    for (int off = 1; off < SCAN_T; off <<= 1) {
        int x = (t >= off) ? sh[t - off] : 0;
        __syncthreads();
        sh[t] += x;
        __syncthreads();
    }
    int thread_excl = sh[t] - s;
    if (t == SCAN_T - 1) g_bsum[b] = sh[t];
    int run = thread_excl;
#pragma unroll
    for (int k = 0; k < 4; k++) {
        int idx = base + k;
        if (idx < N_NODES) g_excl[idx] = run;
        run += v[k];
    }
}

// single-block exclusive scan of block sums (SCAN_NB <= 512)
__global__ void scan2_kernel() {
    __shared__ int sh[512];
    int t = threadIdx.x;
    int orig = (t < SCAN_NB) ? g_bsum[t] : 0;
    sh[t] = orig;
    __syncthreads();
    for (int off = 1; off < 512; off <<= 1) {
        int x = (t >= off) ? sh[t - off] : 0;
        __syncthreads();
        sh[t] += x;
        __syncthreads();
    }
    if (t < SCAN_NB) g_bsum[t] = sh[t] - orig;   // exclusive
}

__global__ void scan3_kernel() {
    int i = blockIdx.x * blockDim.x + threadIdx.x;
    if (i < N_NODES) {
        int p = g_excl[i] + g_bsum[i / SCAN_CHUNK];
        g_ptr[i] = p;
        g_fill[i] = p;
    }
    if (i == 0) g_ptr[N_NODES] = N_EDGES;
}

__global__ void scatter_kernel(const int* __restrict__ ei) {
    int e = blockIdx.x * blockDim.x + threadIdx.x;
    if (e >= N_EDGES) return;
    int s = ei[e];
    int d = ei[N_EDGES + e];
    int pos = atomicAdd(&g_fill[d], 1);
    g_csr_src[pos] = s;
}

// ============ input: state = relu(x@inW+b), msg0 = relu(state@msgW0+b0) ============
__global__ void input_kernel(const float* __restrict__ x,
                             const float* __restrict__ inW,
                             const float* __restrict__ inb,
                             const float* __restrict__ mW,
                             const float* __restrict__ mb) {
    __shared__ float sIW[FEAT * STATE];
    __shared__ float sIb[STATE];
    __shared__ float sMW[STATE * STATE];
    __shared__ float sMb[STATE];
    int t = threadIdx.x;
    if (t < FEAT * STATE) sIW[t] = inW[t];
    if (t < STATE) { sIb[t] = inb[t]; sMb[t] = mb[t]; }
    if (t < STATE * STATE) sMW[t] = mW[t];
    __syncthreads();

    int i = blockIdx.x * blockDim.x + t;
    if (i >= N_NODES) return;

    float xi[FEAT];
#pragma unroll
    for (int k = 0; k < FEAT; k++) xi[k] = x[(size_t)i * FEAT + k];

    float st[STATE];
#pragma unroll
    for (int j = 0; j < STATE; j++) {
        float acc = sIb[j];
#pragma unroll
        for (int k = 0; k < FEAT; k++) acc = fmaf(xi[k], sIW[k * STATE + j], acc);
        st[j] = fmaxf(acc, 0.f);
    }

    float4* sp = reinterpret_cast<float4*>(g_state + (size_t)i * STATE);
#pragma unroll
    for (int v = 0; v < 4; v++)
        sp[v] = make_float4(st[4 * v], st[4 * v + 1], st[4 * v + 2], st[4 * v + 3]);

    float m[STATE];
#pragma unroll
    for (int j = 0; j < STATE; j++) {
        float acc = sMb[j];
#pragma unroll
        for (int k = 0; k < STATE; k++) acc = fmaf(st[k], sMW[k * STATE + j], acc);
        m[j] = fmaxf(acc, 0.f);
    }
    float4* mp = reinterpret_cast<float4*>(g_msg_a + (size_t)i * STATE);
#pragma unroll
    for (int v = 0; v < 4; v++)
        mp[v] = make_float4(m[4 * v], m[4 * v + 1], m[4 * v + 2], m[4 * v + 3]);
}

// ============ fused round: gather agg, update state, emit next msg / readout ============
__global__ void round_kernel(const float* __restrict__ updW,
                             const float* __restrict__ updb,
                             const float* __restrict__ msgW,   // unused if last
                             const float* __restrict__ msgb,
                             const float* __restrict__ msg_in,
                             float* __restrict__ msg_out,
                             int last,
                             const int* __restrict__ batch,
                             const float* __restrict__ outW,
                             float* __restrict__ out) {
    __shared__ float sUW[STATE * STATE];
    __shared__ float sUb[STATE];
    __shared__ float sMW[STATE * STATE];
    __shared__ float sMb[STATE];
    __shared__ float sOW[STATE];
    int t = threadIdx.x;
    if (t < STATE * STATE) {
        sUW[t] = updW[t];
        sMW[t] = last ? 0.f : msgW[t];
    }
    if (t < STATE) {
        sUb[t] = updb[t];
        sMb[t] = last ? 0.f : msgb[t];
        sOW[t] = last ? outW[t] : 0.f;
    }
    __syncthreads();

    int i = blockIdx.x * blockDim.x + t;
    if (i >= N_NODES) return;

    float acc[STATE];
#pragma unroll
    for (int k = 0; k < STATE; k++) acc[k] = 0.f;

    int p0 = g_ptr[i];
    int p1 = g_ptr[i + 1];
    for (int j = p0; j < p1; j++) {
        int s = g_csr_src[j];
        const float4* m = reinterpret_cast<const float4*>(msg_in + (size_t)s * STATE);
        float4 a = m[0], b4 = m[1], c = m[2], d4 = m[3];
        acc[0] += a.x;  acc[1] += a.y;  acc[2] += a.z;  acc[3] += a.w;
        acc[4] += b4.x; acc[5] += b4.y; acc[6] += b4.z; acc[7] += b4.w;
        acc[8] += c.x;  acc[9] += c.y;  acc[10] += c.z; acc[11] += c.w;
        acc[12] += d4.x; acc[13] += d4.y; acc[14] += d4.z; acc[15] += d4.w;
    }

    // load state
    float st[STATE];
    float4* sp = reinterpret_cast<float4*>(g_state + (size_t)i * STATE);
#pragma unroll
    for (int v = 0; v < 4; v++) {
        float4 f = sp[v];
        st[4 * v] = f.x; st[4 * v + 1] = f.y; st[4 * v + 2] = f.z; st[4 * v + 3] = f.w;
    }

    // state += relu(agg @ updW + updb)
#pragma unroll
    for (int j = 0; j < STATE; j++) {
        float u = sUb[j];
#pragma unroll
        for (int k = 0; k < STATE; k++) u = fmaf(acc[k], sUW[k * STATE + j], u);
        st[j] += fmaxf(u, 0.f);
    }

    if (!last) {
        // persist state
#pragma unroll
        for (int v = 0; v < 4; v++)
            sp[v] = make_float4(st[4 * v], st[4 * v + 1], st[4 * v + 2], st[4 * v + 3]);
        // next message
        float m[STATE];
#pragma unroll
        for (int j = 0; j < STATE; j++) {
            float a2 = sMb[j];
#pragma unroll
            for (int k = 0; k < STATE; k++) a2 = fmaf(st[k], sMW[k * STATE + j], a2);
            m[j] = fmaxf(a2, 0.f);
        }
        float4* mp = reinterpret_cast<float4*>(msg_out + (size_t)i * STATE);
#pragma unroll
        for (int v = 0; v < 4; v++)
            mp[v] = make_float4(m[4 * v], m[4 * v + 1], m[4 * v + 2], m[4 * v + 3]);
    } else {
        // readout: out[batch[i]] += state . outW  (state store skipped: dead)
        float dot = 0.f;
#pragma unroll
        for (int k = 0; k < STATE; k++) dot = fmaf(st[k], sOW[k], dot);
        atomicAdd(&out[batch[i]], dot);
    }
}

__global__ void out_init_kernel(const float* __restrict__ out_b, float* __restrict__ out) {
    int g = blockIdx.x * blockDim.x + threadIdx.x;
    if (g < N_GRAPHS) out[g] = out_b[0];
}

extern "C" void kernel_launch(void* const* d_in, const int* in_sizes, int n_in,
                              void* d_out, int out_size) {
    const float* x     = (const float*)d_in[0];
    const int*   ei    = (const int*)d_in[1];
    const int*   batch = (const int*)d_in[2];
    const float* in_W  = (const float*)d_in[3];
    const float* in_b  = (const float*)d_in[4];
    const float* msg_W = (const float*)d_in[5];
    const float* msg_b = (const float*)d_in[6];
    const float* upd_W = (const float*)d_in[7];
    const float* upd_b = (const float*)d_in[8];
    const float* out_W = (const float*)d_in[9];
    const float* out_b = (const float*)d_in[10];
    float* out = (float*)d_out;

    const int TB = 256;
    int node_blocks = (N_NODES + TB - 1) / TB;
    int edge_blocks = (N_EDGES + TB - 1) / TB;

    // CSR build (by dst)
    zero_cnt_kernel<<<node_blocks, TB>>>();
    hist_kernel<<<edge_blocks, TB>>>(ei);
    scan1_kernel<<<SCAN_NB, SCAN_T>>>();
    scan2_kernel<<<1, 512>>>();
    scan3_kernel<<<node_blocks, TB>>>();
    scatter_kernel<<<edge_blocks, TB>>>(ei);

    // input + first message
    input_kernel<<<node_blocks, TB>>>(x, in_W, in_b, msg_W, msg_b);

    // graph output bias init (before last round's fused readout)
    out_init_kernel<<<(N_GRAPHS + TB - 1) / TB, TB>>>(out_b, out);

    // rounds (double-buffered messages)
    float* bufs[2] = {nullptr, nullptr};
    // device symbols: take addresses via kernels' view — use cudaGetSymbolAddress-free trick:
    // we can't call cudaGetSymbolAddress result into capture-unsafe ops, but passing
    // device-symbol-derived pointers as kernel args is fine.
    // Obtain them on host once per launch call:
    void* pa; void* pb;
    cudaGetSymbolAddress(&pa, g_msg_a);
    cudaGetSymbolAddress(&pb, g_msg_b);
    bufs[0] = (float*)pa;
    bufs[1] = (float*)pb;

    for (int r = 0; r < ROUNDS; r++) {
        int last = (r == ROUNDS - 1);
        const float* mW = last ? msg_W : (msg_W + (r + 1) * STATE * STATE);
        const float* mb = last ? msg_b : (msg_b + (r + 1) * STATE);
        round_kernel<<<node_blocks, TB>>>(
            upd_W + r * STATE * STATE, upd_b + r * STATE,
            mW, mb,
            bufs[r & 1], bufs[(r + 1) & 1],
            last, batch, out_W, out);
    }
}

// round 3
// speedup vs baseline: 1.5245x; 1.0778x over previous
#include <cuda_runtime.h>
#include <cstdint>

#define N_NODES 500000
#define N_EDGES 5000000
#define N_GRAPHS 5000
#define FEAT 7
#define STATE 16
#define ROUNDS 4

#define SCAN_CHUNK 1024
#define SCAN_T 256
#define SCAN_NB ((N_NODES + SCAN_CHUNK - 1) / SCAN_CHUNK)   // 489

// ---- scratch (__device__ globals; no allocs allowed) ----
__device__ float g_state[N_NODES * STATE];
__device__ float g_msg_a[N_NODES * STATE];
__device__ float g_msg_b[N_NODES * STATE];
__device__ int   g_cnt[N_NODES];
__device__ int   g_excl[N_NODES];
__device__ int   g_bsum[SCAN_NB];
__device__ int   g_ptr[N_NODES + 1];
__device__ int   g_rank[N_EDGES];
__device__ int   g_csr_src[N_EDGES];

// ================= CSR build =================
__global__ void zero_cnt_kernel() {
    int i = blockIdx.x * blockDim.x + threadIdx.x;
    if (i < N_NODES) g_cnt[i] = 0;
}

// histogram AND per-edge rank (atomic return value reused — no atomic in scatter)
__global__ void hist_kernel(const int* __restrict__ ei) {
    int e = blockIdx.x * blockDim.x + threadIdx.x;
    if (e < N_EDGES) g_rank[e] = atomicAdd(&g_cnt[ei[N_EDGES + e]], 1);
}

// block-local exclusive scan over chunks of 1024 (4 elems/thread)
__global__ void scan1_kernel() {
    __shared__ int sh[SCAN_T];
    int b = blockIdx.x, t = threadIdx.x;
    int base = b * SCAN_CHUNK + t * 4;
    int v[4];
#pragma unroll
    for (int k = 0; k < 4; k++) {
        int idx = base + k;
        v[k] = (idx < N_NODES) ? g_cnt[idx] : 0;
    }
    int s = v[0] + v[1] + v[2] + v[3];
    sh[t] = s;
    __syncthreads();
    for (int off = 1; off < SCAN_T; off <<= 1) {
        int x = (t >= off) ? sh[t - off] : 0;
        __syncthreads();
        sh[t] += x;
        __syncthreads();
    }
    int thread_excl = sh[t] - s;
    if (t == SCAN_T - 1) g_bsum[b] = sh[t];
    int run = thread_excl;
#pragma unroll
    for (int k = 0; k < 4; k++) {
        int idx = base + k;
        if (idx < N_NODES) g_excl[idx] = run;
        run += v[k];
    }
}

// single-block exclusive scan of block sums (SCAN_NB <= 512)
__global__ void scan2_kernel() {
    __shared__ int sh[512];
    int t = threadIdx.x;
    int orig = (t < SCAN_NB) ? g_bsum[t] : 0;
    sh[t] = orig;
    __syncthreads();
    for (int off = 1; off < 512; off <<= 1) {
        int x = (t >= off) ? sh[t - off] : 0;
        __syncthreads();
        sh[t] += x;
        __syncthreads();
    }
    if (t < SCAN_NB) g_bsum[t] = sh[t] - orig;   // exclusive
}

__global__ void scan3_kernel() {
    int i = blockIdx.x * blockDim.x + threadIdx.x;
    if (i < N_NODES) g_ptr[i] = g_excl[i] + g_bsum[i / SCAN_CHUNK];
    if (i == 0) g_ptr[N_NODES] = N_EDGES;
}

__global__ void scatter_kernel(const int* __restrict__ ei) {
    int e = blockIdx.x * blockDim.x + threadIdx.x;
    if (e >= N_EDGES) return;
    int s = ei[e];
    int d = ei[N_EDGES + e];
    g_csr_src[g_ptr[d] + g_rank[e]] = s;
}

// ============ input: state = relu(x@inW+b), msg0 = relu(state@msgW0+b0) ============
__global__ void input_kernel(const float* __restrict__ x,
                             const float* __restrict__ inW,
                             const float* __restrict__ inb,
                             const float* __restrict__ mW,
                             const float* __restrict__ mb) {
    __shared__ float sIW[FEAT * STATE];
    __shared__ float sIb[STATE];
    __shared__ float sMW[STATE * STATE];
    __shared__ float sMb[STATE];
    int t = threadIdx.x;
    if (t < FEAT * STATE) sIW[t] = inW[t];
    if (t < STATE) { sIb[t] = inb[t]; sMb[t] = mb[t]; }
    if (t < STATE * STATE) sMW[t] = mW[t];
    __syncthreads();

    int i = blockIdx.x * blockDim.x + t;
    if (i >= N_NODES) return;

    float xi[FEAT];
#pragma unroll
    for (int k = 0; k < FEAT; k++) xi[k] = x[(size_t)i * FEAT + k];

    float st[STATE];
#pragma unroll
    for (int j = 0; j < STATE; j++) {
        float acc = sIb[j];
#pragma unroll
        for (int k = 0; k < FEAT; k++) acc = fmaf(xi[k], sIW[k * STATE + j], acc);
        st[j] = fmaxf(acc, 0.f);
    }

    float4* sp = reinterpret_cast<float4*>(g_state + (size_t)i * STATE);
#pragma unroll
    for (int v = 0; v < 4; v++)
        sp[v] = make_float4(st[4 * v], st[4 * v + 1], st[4 * v + 2], st[4 * v + 3]);

    float m[STATE];
#pragma unroll
    for (int j = 0; j < STATE; j++) {
        float acc = sMb[j];
#pragma unroll
        for (int k = 0; k < STATE; k++) acc = fmaf(st[k], sMW[k * STATE + j], acc);
        m[j] = fmaxf(acc, 0.f);
    }
    float4* mp = reinterpret_cast<float4*>(g_msg_a + (size_t)i * STATE);
#pragma unroll
    for (int v = 0; v < 4; v++)
        mp[v] = make_float4(m[4 * v], m[4 * v + 1], m[4 * v + 2], m[4 * v + 3]);
}

// ============ fused round: 4 lanes per node ============
// lane group of 4 handles one node; each lane owns state slice [4*lane, 4*lane+4)
#define WSTRIDE 17   // padded row stride for shared weights (conflict-free across lanes)

__global__ void round_kernel(const float* __restrict__ updW,
                             const float* __restrict__ updb,
                             const float* __restrict__ msgW,   // unused if last
                             const float* __restrict__ msgb,
                             const float* __restrict__ msg_in,
                             float* __restrict__ msg_out,
                             int last,
                             const int* __restrict__ batch,
                             const float* __restrict__ outW,
                             float* __restrict__ out) {
    __shared__ float sUW[STATE * WSTRIDE];
    __shared__ float sMW[STATE * WSTRIDE];
    __shared__ float sUb[STATE];
    __shared__ float sMb[STATE];
    __shared__ float sOW[STATE];
    int t = threadIdx.x;
    if (t < STATE * STATE) {
        int r = t >> 4, c = t & 15;
        sUW[r * WSTRIDE + c] = updW[t];
        sMW[r * WSTRIDE + c] = last ? 0.f : msgW[t];
    }
    if (t < STATE) {
        sUb[t] = updb[t];
        sMb[t] = last ? 0.f : msgb[t];
        sOW[t] = last ? outW[t] : 0.f;
    }
    __syncthreads();

    int gtid = blockIdx.x * blockDim.x + t;
    int node = gtid >> 2;
    int lane = gtid & 3;
    if (node >= N_NODES) return;

    int p0 = g_ptr[node];
    int p1 = g_ptr[node + 1];

    // gather: each lane accumulates its float4 slice of sum of messages
    float4 acc = make_float4(0.f, 0.f, 0.f, 0.f);
    for (int j = p0; j < p1; j++) {
        int s = __ldg(&g_csr_src[j]);
        float4 m = __ldg(reinterpret_cast<const float4*>(msg_in + (size_t)s * STATE) + lane);
        acc.x += m.x; acc.y += m.y; acc.z += m.z; acc.w += m.w;
    }

    // GEMV1 partials: u[j] = sum over this lane's k=4*lane..4*lane+3 of acc*W
    const float* uw = sUW + (4 * lane) * WSTRIDE;
    float u[STATE];
#pragma unroll
    for (int j = 0; j < STATE; j++)
        u[j] = fmaf(acc.x, uw[j],
               fmaf(acc.y, uw[WSTRIDE + j],
               fmaf(acc.z, uw[2 * WSTRIDE + j],
                    acc.w * uw[3 * WSTRIDE + j])));
    // butterfly reduce across the 4-lane group
#pragma unroll
    for (int j = 0; j < STATE; j++) {
        u[j] += __shfl_xor_sync(0xFFFFFFFF, u[j], 1);
        u[j] += __shfl_xor_sync(0xFFFFFFFF, u[j], 2);
    }

    // state slice for this lane
    float4 stv = *(reinterpret_cast<const float4*>(g_state + (size_t)node * STATE) + lane);
    float st[4];
    st[0] = stv.x + fmaxf(u[4 * lane + 0] + sUb[4 * lane + 0], 0.f);
    st[1] = stv.y + fmaxf(u[4 * lane + 1] + sUb[4 * lane + 1], 0.f);
    st[2] = stv.z + fmaxf(u[4 * lane + 2] + sUb[4 * lane + 2], 0.f);
    st[3] = stv.w + fmaxf(u[4 * lane + 3] + sUb[4 * lane + 3], 0.f);

    if (!last) {
        // persist state slice
        *(reinterpret_cast<float4*>(g_state + (size_t)node * STATE) + lane) =
            make_float4(st[0], st[1], st[2], st[3]);
        // GEMV2: next message
        const float* mw = sMW + (4 * lane) * WSTRIDE;
        float m[STATE];
#pragma unroll
        for (int j = 0; j < STATE; j++)
            m[j] = fmaf(st[0], mw[j],
                   fmaf(st[1], mw[WSTRIDE + j],
                   fmaf(st[2], mw[2 * WSTRIDE + j],
                        st[3] * mw[3 * WSTRIDE + j])));
#pragma unroll
        for (int j = 0; j < STATE; j++) {
            m[j] += __shfl_xor_sync(0xFFFFFFFF, m[j], 1);
            m[j] += __shfl_xor_sync(0xFFFFFFFF, m[j], 2);
        }
        float4 mv;
        mv.x = fmaxf(m[4 * lane + 0] + sMb[4 * lane + 0], 0.f);
        mv.y = fmaxf(m[4 * lane + 1] + sMb[4 * lane + 1], 0.f);
        mv.z = fmaxf(m[4 * lane + 2] + sMb[4 * lane + 2], 0.f);
        mv.w = fmaxf(m[4 * lane + 3] + sMb[4 * lane + 3], 0.f);
        *(reinterpret_cast<float4*>(msg_out + (size_t)node * STATE) + lane) = mv;
    } else {
        // readout: dot(state, outW) reduced across the 4 lanes
        float dot = fmaf(st[0], sOW[4 * lane + 0],
                    fmaf(st[1], sOW[4 * lane + 1],
                    fmaf(st[2], sOW[4 * lane + 2],
                         st[3] * sOW[4 * lane + 3])));
        dot += __shfl_xor_sync(0xFFFFFFFF, dot, 1);
        dot += __shfl_xor_sync(0xFFFFFFFF, dot, 2);
        if (lane == 0) atomicAdd(&out[batch[node]], dot);
    }
}

__global__ void out_init_kernel(const float* __restrict__ out_b, float* __restrict__ out) {
    int g = blockIdx.x * blockDim.x + threadIdx.x;
    if (g < N_GRAPHS) out[g] = out_b[0];
}

extern "C" void kernel_launch(void* const* d_in, const int* in_sizes, int n_in,
                              void* d_out, int out_size) {
    const float* x     = (const float*)d_in[0];
    const int*   ei    = (const int*)d_in[1];
    const int*   batch = (const int*)d_in[2];
    const float* in_W  = (const float*)d_in[3];
    const float* in_b  = (const float*)d_in[4];
    const float* msg_W = (const float*)d_in[5];
    const float* msg_b = (const float*)d_in[6];
    const float* upd_W = (const float*)d_in[7];
    const float* upd_b = (const float*)d_in[8];
    const float* out_W = (const float*)d_in[9];
    const float* out_b = (const float*)d_in[10];
    float* out = (float*)d_out;

    const int TB = 256;
    int node_blocks = (N_NODES + TB - 1) / TB;
    int edge_blocks = (N_EDGES + TB - 1) / TB;
    int round_blocks = (N_NODES * 4 + TB - 1) / TB;

    // CSR build (by dst); hist returns per-edge rank, so scatter is atomic-free
    zero_cnt_kernel<<<node_blocks, TB>>>();
    hist_kernel<<<edge_blocks, TB>>>(ei);
    scan1_kernel<<<SCAN_NB, SCAN_T>>>();
    scan2_kernel<<<1, 512>>>();
    scan3_kernel<<<node_blocks, TB>>>();
    scatter_kernel<<<edge_blocks, TB>>>(ei);

    // input + first message
    input_kernel<<<node_blocks, TB>>>(x, in_W, in_b, msg_W, msg_b);

    // graph output bias init (before last round's fused readout)
    out_init_kernel<<<(N_GRAPHS + TB - 1) / TB, TB>>>(out_b, out);

    void* pa; void* pb;
    cudaGetSymbolAddress(&pa, g_msg_a);
    cudaGetSymbolAddress(&pb, g_msg_b);
    float* bufs[2] = {(float*)pa, (float*)pb};

    for (int r = 0; r < ROUNDS; r++) {
        int last = (r == ROUNDS - 1);
        const float* mW = last ? msg_W : (msg_W + (r + 1) * STATE * STATE);
        const float* mb = last ? msg_b : (msg_b + (r + 1) * STATE);
        round_kernel<<<round_blocks, TB>>>(
            upd_W + r * STATE * STATE, upd_b + r * STATE,
            mW, mb,
            bufs[r & 1], bufs[(r + 1) & 1],
            last, batch, out_W, out);
    }
}